// round 3
// baseline (speedup 1.0000x reference)
#include <cuda_runtime.h>
#include <cuda_bf16.h>
#include <math.h>

#define N_NODES 100000
#define N_EDGES 1600000
#define F_IN 128
#define HID 64
#define N_CLS 40

// ---------------- scratch (static __device__, no allocations) ----------------
__device__ int   g_is64;
__device__ int   g_cnt[N_NODES];
__device__ int   g_rowptr[N_NODES + 1];
__device__ int   g_bsum[128];
__device__ int   g_boff[128];
__device__ int   g_col[N_EDGES];
__device__ float g_Y[(size_t)N_NODES * 128];   // gemm output [N,128] = [xl | xr]
__device__ float g_H[(size_t)N_NODES * 64];    // hidden state [N,64]
__device__ float g_Wc1[128 * 128];             // [W1l;W1r] rows, K=128
__device__ float g_Wc2[128 * 64];              // [W2l;W2r] rows, K=64
__device__ float g_Wc3[128 * 64];              // [W3l;W3r] rows, K=64
__device__ float g_Wco[64 * 64];               // Wout padded 40->64 rows, K=64

// ---------------- edge dtype detection ----------------
// int64 node ids (< 2^31) have zero at every odd 32-bit word; int32 random ids
// in [0, 100000) are nonzero at odd word positions with overwhelming probability.
__global__ void detect_kernel(const int* __restrict__ ei_words)
{
    __shared__ int nonzero_odd;
    if (threadIdx.x == 0) nonzero_odd = 0;
    __syncthreads();
    // scan first 4096 words (covers 2048 int64 or 4096 int32 entries)
    for (int i = threadIdx.x; i < 4096; i += blockDim.x) {
        if ((i & 1) && ei_words[i] != 0) nonzero_odd = 1;
    }
    __syncthreads();
    if (threadIdx.x == 0) g_is64 = (nonzero_odd == 0) ? 1 : 0;
}

__device__ __forceinline__ int edge_fetch(const void* ei, long long pos)
{
    int v;
    if (g_is64) v = (int)((const long long*)ei)[pos];
    else        v = ((const int*)ei)[pos];
    return v;
}

// ---------------- CSR build ----------------
__global__ void zero_cnt()
{
    int i = blockIdx.x * blockDim.x + threadIdx.x;
    if (i < N_NODES) g_cnt[i] = 0;
}

__global__ void hist_kernel(const void* __restrict__ ei)
{
    int e = blockIdx.x * blockDim.x + threadIdx.x;
    if (e < N_EDGES) {
        int d = edge_fetch(ei, (long long)N_EDGES + e);   // dst
        if ((unsigned)d < (unsigned)N_NODES) atomicAdd(&g_cnt[d], 1);
    }
}

__global__ void scan1()
{
    __shared__ int s[1024];
    int t = threadIdx.x;
    int i = blockIdx.x * 1024 + t;
    int v = (i < N_NODES) ? g_cnt[i] : 0;
    s[t] = v;
    __syncthreads();
    for (int off = 1; off < 1024; off <<= 1) {
        int x = (t >= off) ? s[t - off] : 0;
        __syncthreads();
        s[t] += x;
        __syncthreads();
    }
    if (i < N_NODES) g_rowptr[i] = s[t] - v;   // exclusive partial
    if (t == 1023) g_bsum[blockIdx.x] = s[t];
}

__global__ void scan2(int nblocks)
{
    __shared__ int s[128];
    int t = threadIdx.x;
    int v = (t < nblocks) ? g_bsum[t] : 0;
    s[t] = v;
    __syncthreads();
    for (int off = 1; off < 128; off <<= 1) {
        int x = (t >= off) ? s[t - off] : 0;
        __syncthreads();
        s[t] += x;
        __syncthreads();
    }
    g_boff[t] = s[t] - v;   // exclusive
}

__global__ void scan3()
{
    int i = blockIdx.x * blockDim.x + threadIdx.x;
    if (i < N_NODES) g_rowptr[i] += g_boff[i >> 10];
    else if (i == N_NODES) g_rowptr[N_NODES] = N_EDGES;
}

__global__ void fill_kernel(const void* __restrict__ ei)
{
    int e = blockIdx.x * blockDim.x + threadIdx.x;
    if (e < N_EDGES) {
        int d = edge_fetch(ei, (long long)N_EDGES + e);   // dst
        int s = edge_fetch(ei, e);                         // src
        if ((unsigned)d < (unsigned)N_NODES && (unsigned)s < (unsigned)N_NODES) {
            int pos = g_rowptr[d] + atomicAdd(&g_cnt[d], 1);
            if ((unsigned)pos < (unsigned)N_EDGES) g_col[pos] = s;
        }
    }
}

// ---------------- weight prep ----------------
__global__ void prep_weights(const float* __restrict__ W1l, const float* __restrict__ W1r,
                             const float* __restrict__ W2l, const float* __restrict__ W2r,
                             const float* __restrict__ W3l, const float* __restrict__ W3r,
                             const float* __restrict__ Wout)
{
    int i = blockIdx.x * blockDim.x + threadIdx.x;
    if (i < 128 * 128) {
        int row = i >> 7, k = i & 127;
        g_Wc1[i] = (row < 64) ? W1l[row * 128 + k] : W1r[(row - 64) * 128 + k];
    }
    if (i < 128 * 64) {
        int row = i >> 6, k = i & 63;
        g_Wc2[i] = (row < 64) ? W2l[row * 64 + k] : W2r[(row - 64) * 64 + k];
        g_Wc3[i] = (row < 64) ? W3l[row * 64 + k] : W3r[(row - 64) * 64 + k];
    }
    if (i < 64 * 64) {
        int row = i >> 6, k = i & 63;
        g_Wco[i] = (row < N_CLS) ? Wout[row * 64 + k] : 0.0f;
    }
}

// ---------------- tiled SGEMM: Y[N, BN] = X[N, K] @ W[BN, K]^T ----------------
template <int K, int BN, int STORE_COLS, int WSEL, bool SRC_EXT, bool DST_EXT>
__global__ void gemm_kernel(const float* __restrict__ Xext,
                            const float* __restrict__ bias,
                            float* __restrict__ Yext,
                            int outStride, int N)
{
    const float* __restrict__ X = SRC_EXT ? Xext : (const float*)g_H;
    const float* __restrict__ W =
        (WSEL == 1) ? (const float*)g_Wc1 :
        (WSEL == 2) ? (const float*)g_Wc2 :
        (WSEL == 3) ? (const float*)g_Wc3 : (const float*)g_Wco;
    float* __restrict__ Y = DST_EXT ? Yext : (float*)g_Y;

    constexpr int BM = 64, BK = 16;
    constexpr int TM = 4, TN = BN / 16;
    __shared__ float As[BK][BM + 4];
    __shared__ float Bs[BK][BN + 4];

    const int tid = threadIdx.x;
    const int tx = tid & 15, ty = tid >> 4;
    const int rowBase = blockIdx.x * BM;

    float acc[TM][TN];
#pragma unroll
    for (int i = 0; i < TM; i++)
#pragma unroll
        for (int j = 0; j < TN; j++) acc[i][j] = 0.0f;

    for (int k0 = 0; k0 < K; k0 += BK) {
        // A tile: 64 rows x 16 k -> one float4 per thread
        {
            int row = tid >> 2;
            int kq = tid & 3;
            float4 v = make_float4(0.f, 0.f, 0.f, 0.f);
            int grow = rowBase + row;
            if (grow < N)
                v = *reinterpret_cast<const float4*>(X + (size_t)grow * K + k0 + kq * 4);
            As[kq * 4 + 0][row] = v.x;
            As[kq * 4 + 1][row] = v.y;
            As[kq * 4 + 2][row] = v.z;
            As[kq * 4 + 3][row] = v.w;
        }
        // B tile: BN rows x 16 k
#pragma unroll
        for (int r = 0; r < (BN * 4) / 256; r++) {
            int t = tid + r * 256;
            int col = t >> 2;
            int kq = t & 3;
            float4 v = *reinterpret_cast<const float4*>(W + (size_t)col * K + k0 + kq * 4);
            Bs[kq * 4 + 0][col] = v.x;
            Bs[kq * 4 + 1][col] = v.y;
            Bs[kq * 4 + 2][col] = v.z;
            Bs[kq * 4 + 3][col] = v.w;
        }
        __syncthreads();
#pragma unroll
        for (int k = 0; k < BK; k++) {
            float a[TM], b[TN];
#pragma unroll
            for (int i = 0; i < TM; i++) a[i] = As[k][ty * TM + i];
#pragma unroll
            for (int j = 0; j < TN; j++) b[j] = Bs[k][tx * TN + j];
#pragma unroll
            for (int i = 0; i < TM; i++)
#pragma unroll
                for (int j = 0; j < TN; j++) acc[i][j] = fmaf(a[i], b[j], acc[i][j]);
        }
        __syncthreads();
    }

#pragma unroll
    for (int i = 0; i < TM; i++) {
        int row = rowBase + ty * TM + i;
        if (row >= N) continue;
#pragma unroll
        for (int j = 0; j < TN; j++) {
            int c = tx * TN + j;
            if (c < STORE_COLS) {
                float v = acc[i][j];
                if (bias) v += bias[c];
                Y[(size_t)row * outStride + c] = v;
            }
        }
    }
}

// ---------------- aggregation: H = [elu]( mean(xl[neigh]) + xr + b ) ----------------
template <bool ELU>
__global__ void agg_kernel(const float* __restrict__ b)   // bias [64]
{
    const float* __restrict__ Y = (const float*)g_Y;  // [N,128]: xl cols 0..63, xr 64..127
    float* __restrict__ H = (float*)g_H;              // [N,64]

    int warp = (blockIdx.x * blockDim.x + threadIdx.x) >> 5;
    int lane = threadIdx.x & 31;
    if (warp >= N_NODES) return;

    int s = g_rowptr[warp];
    int e = g_rowptr[warp + 1];

    float accx = 0.f, accy = 0.f;
    for (int base = s; base < e; base += 32) {
        int idx = base + lane;
        int myc = (idx < e) ? g_col[idx] : 0;
        int n = min(32, e - base);
        for (int j = 0; j < n; j++) {
            int c = __shfl_sync(0xffffffffu, myc, j);
            float2 v = *reinterpret_cast<const float2*>(Y + (size_t)c * 128 + lane * 2);
            accx += v.x;
            accy += v.y;
        }
    }

    int deg = e - s;
    float inv = 1.0f / (float)(deg > 0 ? deg : 1);
    float2 xr = *reinterpret_cast<const float2*>(Y + (size_t)warp * 128 + 64 + lane * 2);
    float rx = accx * inv + xr.x + b[lane * 2];
    float ry = accy * inv + xr.y + b[lane * 2 + 1];
    if (ELU) {
        rx = rx > 0.f ? rx : expm1f(rx);
        ry = ry > 0.f ? ry : expm1f(ry);
    }
    float2 out = make_float2(rx, ry);
    *reinterpret_cast<float2*>(H + (size_t)warp * 64 + lane * 2) = out;
}

// ---------------- launch ----------------
extern "C" void kernel_launch(void* const* d_in, const int* in_sizes, int n_in,
                              void* d_out, int out_size)
{
    const float* x   = (const float*)d_in[0];
    const void*  ei  = d_in[1];                 // int32 or int64, detected on device
    const float* W1l = (const float*)d_in[2];
    const float* b1  = (const float*)d_in[3];
    const float* W1r = (const float*)d_in[4];
    const float* W2l = (const float*)d_in[5];
    const float* b2  = (const float*)d_in[6];
    const float* W2r = (const float*)d_in[7];
    const float* W3l = (const float*)d_in[8];
    const float* b3  = (const float*)d_in[9];
    const float* W3r = (const float*)d_in[10];
    const float* Wout = (const float*)d_in[11];
    const float* bout = (const float*)d_in[12];
    float* out = (float*)d_out;

    const int scanBlocks = (N_NODES + 1023) / 1024;  // 98

    detect_kernel<<<1, 256>>>((const int*)ei);
    prep_weights<<<64, 256>>>(W1l, W1r, W2l, W2r, W3l, W3r, Wout);

    // CSR build
    zero_cnt<<<(N_NODES + 255) / 256, 256>>>();
    hist_kernel<<<(N_EDGES + 255) / 256, 256>>>(ei);
    scan1<<<scanBlocks, 1024>>>();
    scan2<<<1, 128>>>(scanBlocks);
    scan3<<<(N_NODES + 256) / 256, 256>>>();
    zero_cnt<<<(N_NODES + 255) / 256, 256>>>();
    fill_kernel<<<(N_EDGES + 255) / 256, 256>>>(ei);

    const int gemmGrid = (N_NODES + 63) / 64;        // 1563
    const int aggGrid  = (N_NODES * 32 + 255) / 256; // 12500

    // Layer 1: Y = x @ [W1l;W1r]^T   (external src, internal dst)
    gemm_kernel<128, 128, 128, 1, true, false><<<gemmGrid, 256>>>(x, nullptr, nullptr, 128, N_NODES);
    agg_kernel<true><<<aggGrid, 256>>>(b1);
    // Layer 2
    gemm_kernel<64, 128, 128, 2, false, false><<<gemmGrid, 256>>>(nullptr, nullptr, nullptr, 128, N_NODES);
    agg_kernel<true><<<aggGrid, 256>>>(b2);
    // Layer 3
    gemm_kernel<64, 128, 128, 3, false, false><<<gemmGrid, 256>>>(nullptr, nullptr, nullptr, 128, N_NODES);
    agg_kernel<false><<<aggGrid, 256>>>(b3);
    // Head: writes d_out directly with bias
    gemm_kernel<64, 64, N_CLS, 4, false, true><<<gemmGrid, 256>>>(nullptr, bout, out, N_CLS, N_NODES);
}

// round 4
// speedup vs baseline: 1.3867x; 1.3867x over previous
#include <cuda_runtime.h>
#include <cuda_bf16.h>
#include <math.h>

#define N_NODES 100000
#define N_EDGES 1600000
#define F_IN 128
#define HID 64
#define N_CLS 40

// ---------------- scratch (static __device__, no allocations) ----------------
__device__ int   g_is64;
__device__ int   g_cnt[N_NODES];
__device__ int   g_rowptr[N_NODES + 1];
__device__ int   g_bsum[128];
__device__ int   g_boff[128];
__device__ int   g_col[N_EDGES];
__device__ float g_Y[(size_t)N_NODES * 128];   // gemm output [N,128] = [xl | xr]
__device__ float g_H[(size_t)N_NODES * 64];    // hidden state [N,64]
__device__ float g_Wc1[128 * 128];             // [W1l;W1r] rows, K=128
__device__ float g_Wc2[128 * 64];              // [W2l;W2r] rows, K=64
__device__ float g_Wc3[128 * 64];              // [W3l;W3r] rows, K=64
__device__ float g_Wco[64 * 64];               // Wout padded 40->64 rows, K=64

// ---------------- f32x2 packed helpers ----------------
__device__ __forceinline__ unsigned long long pack_dup(float a)
{
    unsigned long long d;
    asm("mov.b64 %0, {%1, %1};" : "=l"(d) : "f"(a));
    return d;
}
__device__ __forceinline__ unsigned long long pack2(float x, float y)
{
    unsigned long long d;
    asm("mov.b64 %0, {%1, %2};" : "=l"(d) : "f"(x), "f"(y));
    return d;
}
__device__ __forceinline__ void ffma2(unsigned long long& d,
                                      unsigned long long a,
                                      unsigned long long b)
{
    asm("fma.rn.f32x2 %0, %1, %2, %0;" : "+l"(d) : "l"(a), "l"(b));
}
__device__ __forceinline__ float2 unpack2(unsigned long long v)
{
    float2 u;
    asm("mov.b64 {%0, %1}, %2;" : "=f"(u.x), "=f"(u.y) : "l"(v));
    return u;
}

// ---------------- edge dtype detection ----------------
__global__ void detect_kernel(const int* __restrict__ ei_words)
{
    __shared__ int nonzero_odd;
    if (threadIdx.x == 0) nonzero_odd = 0;
    __syncthreads();
    for (int i = threadIdx.x; i < 4096; i += blockDim.x) {
        if ((i & 1) && ei_words[i] != 0) nonzero_odd = 1;
    }
    __syncthreads();
    if (threadIdx.x == 0) g_is64 = (nonzero_odd == 0) ? 1 : 0;
}

__device__ __forceinline__ int edge_fetch(const void* ei, long long pos)
{
    int v;
    if (g_is64) v = (int)((const long long*)ei)[pos];
    else        v = ((const int*)ei)[pos];
    return v;
}

// ---------------- CSR build ----------------
__global__ void zero_cnt()
{
    int i = blockIdx.x * blockDim.x + threadIdx.x;
    if (i < N_NODES) g_cnt[i] = 0;
}

__global__ void hist_kernel(const void* __restrict__ ei)
{
    int e = blockIdx.x * blockDim.x + threadIdx.x;
    if (e < N_EDGES) {
        int d = edge_fetch(ei, (long long)N_EDGES + e);   // dst
        if ((unsigned)d < (unsigned)N_NODES) atomicAdd(&g_cnt[d], 1);
    }
}

__global__ void scan1()
{
    __shared__ int s[1024];
    int t = threadIdx.x;
    int i = blockIdx.x * 1024 + t;
    int v = (i < N_NODES) ? g_cnt[i] : 0;
    s[t] = v;
    __syncthreads();
    for (int off = 1; off < 1024; off <<= 1) {
        int x = (t >= off) ? s[t - off] : 0;
        __syncthreads();
        s[t] += x;
        __syncthreads();
    }
    if (i < N_NODES) g_rowptr[i] = s[t] - v;   // exclusive partial
    if (t == 1023) g_bsum[blockIdx.x] = s[t];
}

__global__ void scan2(int nblocks)
{
    __shared__ int s[128];
    int t = threadIdx.x;
    int v = (t < nblocks) ? g_bsum[t] : 0;
    s[t] = v;
    __syncthreads();
    for (int off = 1; off < 128; off <<= 1) {
        int x = (t >= off) ? s[t - off] : 0;
        __syncthreads();
        s[t] += x;
        __syncthreads();
    }
    g_boff[t] = s[t] - v;   // exclusive
}

// also zeroes g_cnt for the fill pass (saves a launch)
__global__ void scan3()
{
    int i = blockIdx.x * blockDim.x + threadIdx.x;
    if (i < N_NODES) {
        g_rowptr[i] += g_boff[i >> 10];
        g_cnt[i] = 0;
    } else if (i == N_NODES) {
        g_rowptr[N_NODES] = N_EDGES;
    }
}

__global__ void fill_kernel(const void* __restrict__ ei)
{
    int e = blockIdx.x * blockDim.x + threadIdx.x;
    if (e < N_EDGES) {
        int d = edge_fetch(ei, (long long)N_EDGES + e);   // dst
        int s = edge_fetch(ei, e);                         // src
        if ((unsigned)d < (unsigned)N_NODES && (unsigned)s < (unsigned)N_NODES) {
            int pos = g_rowptr[d] + atomicAdd(&g_cnt[d], 1);
            if ((unsigned)pos < (unsigned)N_EDGES) g_col[pos] = s;
        }
    }
}

// ---------------- weight prep ----------------
__global__ void prep_weights(const float* __restrict__ W1l, const float* __restrict__ W1r,
                             const float* __restrict__ W2l, const float* __restrict__ W2r,
                             const float* __restrict__ W3l, const float* __restrict__ W3r,
                             const float* __restrict__ Wout)
{
    int i = blockIdx.x * blockDim.x + threadIdx.x;
    if (i < 128 * 128) {
        int row = i >> 7, k = i & 127;
        g_Wc1[i] = (row < 64) ? W1l[row * 128 + k] : W1r[(row - 64) * 128 + k];
    }
    if (i < 128 * 64) {
        int row = i >> 6, k = i & 63;
        g_Wc2[i] = (row < 64) ? W2l[row * 64 + k] : W2r[(row - 64) * 64 + k];
        g_Wc3[i] = (row < 64) ? W3l[row * 64 + k] : W3r[(row - 64) * 64 + k];
    }
    if (i < 64 * 64) {
        int row = i >> 6, k = i & 63;
        g_Wco[i] = (row < N_CLS) ? Wout[row * 64 + k] : 0.0f;
    }
}

// ---------------- f32x2 SGEMM: Y[N, BN] = X[N, K] @ W[BN, K]^T ----------------
// BM=128, BK=32, 256 threads, 8x8 (or 8x4) microtile, packed-pair accumulators.
// Rows/cols split into two 4-wide halves (offset 0 and 64) for conflict-free LDS.128.
template <int K, int BN, int STORE_COLS, int WSEL, bool SRC_EXT, bool DST_EXT, bool BIAS>
__global__ void __launch_bounds__(256, 2)
gemm2_kernel(const float* __restrict__ Xext,
             const float* __restrict__ bias,
             float* __restrict__ Yext,
             int outStride, int N)
{
    const float* __restrict__ X = SRC_EXT ? Xext : (const float*)g_H;
    const float* __restrict__ W =
        (WSEL == 1) ? (const float*)g_Wc1 :
        (WSEL == 2) ? (const float*)g_Wc2 :
        (WSEL == 3) ? (const float*)g_Wc3 : (const float*)g_Wco;
    float* __restrict__ Y = DST_EXT ? Yext : (float*)g_Y;

    constexpr int BM = 128, BK = 32;
    constexpr int NH = BN / 64;            // 2 for BN=128, 1 for BN=64
    __shared__ float As[BK][BM + 4];
    __shared__ float Bs[BK][BN + 4];

    const int tid = threadIdx.x;
    const int tx = tid & 15;               // 16 col-groups
    const int ty = tid >> 4;               // 16 row-groups
    const int rowBase = blockIdx.x * BM;

    unsigned long long acc[2][4][NH][2];
#pragma unroll
    for (int mi = 0; mi < 2; mi++)
#pragma unroll
        for (int ii = 0; ii < 4; ii++)
#pragma unroll
            for (int ni = 0; ni < NH; ni++) {
                acc[mi][ii][ni][0] = 0ull;
                acc[mi][ii][ni][1] = 0ull;
            }

    const int lrow = tid >> 3;             // 0..31
    const int lkq  = tid & 7;              // 0..7 -> 4 floats each = 32 k

    for (int k0 = 0; k0 < K; k0 += BK) {
        __syncthreads();
        // load A chunk: BM x BK
#pragma unroll
        for (int r = 0; r < BM / 32; r++) {
            int row = r * 32 + lrow;
            int grow = rowBase + row;
            if (grow >= N) grow = 0;       // safe load; result rows discarded at store
            float4 v = *reinterpret_cast<const float4*>(X + (size_t)grow * K + k0 + lkq * 4);
            As[lkq * 4 + 0][row] = v.x;
            As[lkq * 4 + 1][row] = v.y;
            As[lkq * 4 + 2][row] = v.z;
            As[lkq * 4 + 3][row] = v.w;
        }
        // load B chunk: BN x BK
#pragma unroll
        for (int r = 0; r < BN / 32; r++) {
            int n = r * 32 + lrow;
            float4 v = *reinterpret_cast<const float4*>(W + (size_t)n * K + k0 + lkq * 4);
            Bs[lkq * 4 + 0][n] = v.x;
            Bs[lkq * 4 + 1][n] = v.y;
            Bs[lkq * 4 + 2][n] = v.z;
            Bs[lkq * 4 + 3][n] = v.w;
        }
        __syncthreads();

#pragma unroll 8
        for (int k = 0; k < BK; k++) {
            float4 a0 = *reinterpret_cast<const float4*>(&As[k][ty * 4]);
            float4 a1 = *reinterpret_cast<const float4*>(&As[k][64 + ty * 4]);
            unsigned long long bb[NH][2];
#pragma unroll
            for (int ni = 0; ni < NH; ni++) {
                float4 bv = *reinterpret_cast<const float4*>(&Bs[k][ni * 64 + tx * 4]);
                bb[ni][0] = pack2(bv.x, bv.y);
                bb[ni][1] = pack2(bv.z, bv.w);
            }
            float am[2][4] = {{a0.x, a0.y, a0.z, a0.w}, {a1.x, a1.y, a1.z, a1.w}};
#pragma unroll
            for (int mi = 0; mi < 2; mi++)
#pragma unroll
                for (int ii = 0; ii < 4; ii++) {
                    unsigned long long ad = pack_dup(am[mi][ii]);
#pragma unroll
                    for (int ni = 0; ni < NH; ni++) {
                        ffma2(acc[mi][ii][ni][0], ad, bb[ni][0]);
                        ffma2(acc[mi][ii][ni][1], ad, bb[ni][1]);
                    }
                }
        }
    }

    // store
#pragma unroll
    for (int mi = 0; mi < 2; mi++)
#pragma unroll
        for (int ii = 0; ii < 4; ii++) {
            int row = rowBase + mi * 64 + ty * 4 + ii;
            if (row >= N) continue;
#pragma unroll
            for (int ni = 0; ni < NH; ni++)
#pragma unroll
                for (int j2 = 0; j2 < 2; j2++) {
                    int c = ni * 64 + tx * 4 + j2 * 2;
                    float2 u = unpack2(acc[mi][ii][ni][j2]);
                    if (c < STORE_COLS)
                        Y[(size_t)row * outStride + c] = BIAS ? (u.x + bias[c]) : u.x;
                    if (c + 1 < STORE_COLS)
                        Y[(size_t)row * outStride + c + 1] = BIAS ? (u.y + bias[c + 1]) : u.y;
                }
        }
}

// ---------------- aggregation: H = [elu]( mean(xl[neigh]) + xr + b ) ----------------
template <bool ELU>
__global__ void agg_kernel(const float* __restrict__ b)   // bias [64]
{
    const float* __restrict__ Y = (const float*)g_Y;  // [N,128]: xl cols 0..63, xr 64..127
    float* __restrict__ H = (float*)g_H;              // [N,64]

    int warp = (blockIdx.x * blockDim.x + threadIdx.x) >> 5;
    int lane = threadIdx.x & 31;
    if (warp >= N_NODES) return;

    int s = g_rowptr[warp];
    int e = g_rowptr[warp + 1];

    float accx = 0.f, accy = 0.f;
    for (int base = s; base < e; base += 32) {
        int idx = base + lane;
        int myc = (idx < e) ? g_col[idx] : 0;
        int n = min(32, e - base);
        for (int j = 0; j < n; j++) {
            int c = __shfl_sync(0xffffffffu, myc, j);
            float2 v = *reinterpret_cast<const float2*>(Y + (size_t)c * 128 + lane * 2);
            accx += v.x;
            accy += v.y;
        }
    }

    int deg = e - s;
    float inv = 1.0f / (float)(deg > 0 ? deg : 1);
    float2 xr = *reinterpret_cast<const float2*>(Y + (size_t)warp * 128 + 64 + lane * 2);
    float rx = accx * inv + xr.x + b[lane * 2];
    float ry = accy * inv + xr.y + b[lane * 2 + 1];
    if (ELU) {
        rx = rx > 0.f ? rx : expm1f(rx);
        ry = ry > 0.f ? ry : expm1f(ry);
    }
    float2 out = make_float2(rx, ry);
    *reinterpret_cast<float2*>(H + (size_t)warp * 64 + lane * 2) = out;
}

// ---------------- launch ----------------
extern "C" void kernel_launch(void* const* d_in, const int* in_sizes, int n_in,
                              void* d_out, int out_size)
{
    const float* x   = (const float*)d_in[0];
    const void*  ei  = d_in[1];                 // int32 or int64, detected on device
    const float* W1l = (const float*)d_in[2];
    const float* b1  = (const float*)d_in[3];
    const float* W1r = (const float*)d_in[4];
    const float* W2l = (const float*)d_in[5];
    const float* b2  = (const float*)d_in[6];
    const float* W2r = (const float*)d_in[7];
    const float* W3l = (const float*)d_in[8];
    const float* b3  = (const float*)d_in[9];
    const float* W3r = (const float*)d_in[10];
    const float* Wout = (const float*)d_in[11];
    const float* bout = (const float*)d_in[12];
    float* out = (float*)d_out;

    const int scanBlocks = (N_NODES + 1023) / 1024;  // 98

    detect_kernel<<<1, 256>>>((const int*)ei);
    prep_weights<<<64, 256>>>(W1l, W1r, W2l, W2r, W3l, W3r, Wout);

    // CSR build
    zero_cnt<<<(N_NODES + 255) / 256, 256>>>();
    hist_kernel<<<(N_EDGES + 255) / 256, 256>>>(ei);
    scan1<<<scanBlocks, 1024>>>();
    scan2<<<1, 128>>>(scanBlocks);
    scan3<<<(N_NODES + 256) / 256, 256>>>();     // also zeroes g_cnt
    fill_kernel<<<(N_EDGES + 255) / 256, 256>>>(ei);

    const int gemmGrid = (N_NODES + 127) / 128;      // 782
    const int aggGrid  = (N_NODES * 32 + 255) / 256; // 12500

    // Layer 1: Y = x @ [W1l;W1r]^T   (external src, internal dst)
    gemm2_kernel<128, 128, 128, 1, true, false, false><<<gemmGrid, 256>>>(x, nullptr, nullptr, 128, N_NODES);
    agg_kernel<true><<<aggGrid, 256>>>(b1);
    // Layer 2
    gemm2_kernel<64, 128, 128, 2, false, false, false><<<gemmGrid, 256>>>(nullptr, nullptr, nullptr, 128, N_NODES);
    agg_kernel<true><<<aggGrid, 256>>>(b2);
    // Layer 3
    gemm2_kernel<64, 128, 128, 3, false, false, false><<<gemmGrid, 256>>>(nullptr, nullptr, nullptr, 128, N_NODES);
    agg_kernel<false><<<aggGrid, 256>>>(b3);
    // Head: writes d_out directly with bias
    gemm2_kernel<64, 64, N_CLS, 4, false, true, true><<<gemmGrid, 256>>>(nullptr, bout, out, N_CLS, N_NODES);
}